// round 5
// baseline (speedup 1.0000x reference)
#include <cuda_runtime.h>

#define TT 8192
#define H 512
#define NCTA 64
#define NTHREADS 256
#define PAD 32                  // one 128B line per flag
#define FULLMASK 0xffffffffu

typedef unsigned long long u64;

// ---------------- static scratch (no allocations) ----------------
__device__ float g_hist[TT * H];      // layer-0 h history (16 MB) - append-only
__device__ float g_hist2[TT * H];     // layer-1 h history (16 MB) - append-only
__device__ unsigned g_prog0[NCTA * PAD];
__device__ unsigned g_prog1[NCTA * PAD];

// ---------------- helpers ----------------
struct ULL2 { u64 x, y; };

__device__ __forceinline__ ULL2 ldg2(const float* p) {   // 4 floats -> 2 packed f32x2
    ULL2 v; asm("ld.global.nc.v2.u64 {%0,%1},[%2];" : "=l"(v.x), "=l"(v.y) : "l"(p)); return v;
}
__device__ __forceinline__ ULL2 ldcg2(const float* p) {  // L2-coherent
    ULL2 v; asm volatile("ld.global.cg.v2.u64 {%0,%1},[%2];" : "=l"(v.x), "=l"(v.y) : "l"(p)); return v;
}
__device__ __forceinline__ void unpack2(u64 v, float& lo, float& hi) {
    asm("mov.b64 {%0,%1},%2;" : "=f"(lo), "=f"(hi) : "l"(v));
}
__device__ __forceinline__ void fma2(u64& acc, u64 a, u64 b) {   // 2 MACs/instr
    asm("fma.rn.f32x2 %0,%1,%2,%0;" : "+l"(acc) : "l"(a), "l"(b));
}
__device__ __forceinline__ unsigned ldacq(const unsigned* p) {
    unsigned v; asm volatile("ld.acquire.gpu.u32 %0,[%1];" : "=r"(v) : "l"(p)); return v;
}
__device__ __forceinline__ void stcgf(float* p, float v) {
    asm volatile("st.global.cg.f32 [%0],%1;" :: "l"(p), "f"(v));
}
__device__ __forceinline__ void strel(unsigned* p, unsigned v) {
    asm volatile("st.release.gpu.u32 [%0],%1;" :: "l"(p), "r"(v));
}
__device__ __forceinline__ float tanhfast(float x) {
    float y; asm("tanh.approx.f32 %0,%1;" : "=f"(y) : "f"(x)); return y;
}
__device__ __forceinline__ float sigfast(float x) { return 0.5f * tanhfast(0.5f * x) + 0.5f; }

// warp-0-only: spin until all 64 per-CTA flags >= tgt (each on its own line)
__device__ __forceinline__ void wait64(const unsigned* prog, unsigned tgt) {
    const int l = threadIdx.x & 31;
    const unsigned* p0 = prog + l * PAD;
    const unsigned* p1 = prog + (32 + l) * PAD;
    for (;;) {
        unsigned a = ldacq(p0);
        unsigned b = ldacq(p1);
        if (__all_sync(FULLMASK, (a >= tgt) & (b >= tgt))) return;
    }
}

__global__ void init_kernel() {
    int t = threadIdx.x;
    for (int i = t; i < NCTA * PAD; i += blockDim.x) { g_prog0[i] = 0u; g_prog1[i] = 0u; }
}

// ---------------- persistent LSTM layer ----------------
// 64 CTAs x 256 threads. Warp wu owns output j = b*8+wu (gate rows {j,H+j,2H+j,3H+j});
// lane l: sec = l>>3 (i/f/g/o), cg = l&7 (64-column chunk).
template <int LAYER>
__global__ void __launch_bounds__(NTHREADS, 1) lstm_kernel(
    const float* __restrict__ x,
    const float* __restrict__ w_ih, const float* __restrict__ w_hh,
    const float* __restrict__ b_ih, const float* __restrict__ b_hh)
{
    const int tid = threadIdx.x;
    const int wu  = tid >> 5;
    const int l   = tid & 31;
    const int cg  = l & 7;
    const int b   = blockIdx.x;
    const int j   = b * 8 + wu;
    const int row = (l >> 3) * H + j;
    const int coff = cg * 64;

    float* const hist = (LAYER == 0) ? g_hist : g_hist2;
    unsigned* const flags = (LAYER == 0) ? g_prog0 : g_prog1;

    __shared__ float sx[(LAYER == 0) ? TT : 1];
    if (LAYER == 0) for (int i = tid; i < TT; i += NTHREADS) sx[i] = x[i];

    // recurrent weights -> registers (64 floats = 32 packed f32x2)
    u64 rw[32];
    {
        const float* p = w_hh + (size_t)row * H + coff;
#pragma unroll
        for (int k = 0; k < 16; k++) { ULL2 v = ldg2(p + 4 * k); rw[2*k] = v.x; rw[2*k+1] = v.y; }
    }
    u64 riw[32];
    if (LAYER == 1) {
        const float* p = w_ih + (size_t)row * H + coff;
#pragma unroll
        for (int k = 0; k < 16; k++) { ULL2 v = ldg2(p + 4 * k); riw[2*k] = v.x; riw[2*k+1] = v.y; }
    }

    const float bi = b_ih[j]       + b_hh[j];
    const float bf = b_ih[H + j]   + b_hh[H + j];
    const float bg = b_ih[2*H + j] + b_hh[2*H + j];
    const float bo = b_ih[3*H + j] + b_hh[3*H + j];
    float wxi = 0.f, wxf = 0.f, wxg = 0.f, wxo = 0.f;   // NC = 1
    if (LAYER == 0) { wxi = w_ih[j]; wxf = w_ih[H + j]; wxg = w_ih[2*H + j]; wxo = w_ih[3*H + j]; }

    // layer 1: xp(0) = W_ih . h1[0] (previous kernel done -> plain nc loads)
    u64 i0 = 0ull, i1 = 0ull;
    if (LAYER == 1) {
        const float* hb = g_hist + coff;
#pragma unroll
        for (int k = 0; k < 16; k++) {
            ULL2 hv = ldg2(hb + 4 * k);
            fma2(i0, riw[2*k], hv.x); fma2(i1, riw[2*k+1], hv.y);
        }
    }
    float c = 0.0f;    // cell state (replicated across lanes; identical inputs)
    __syncthreads();

    for (int t = 0; t < TT; t++) {
        u64 a0 = (LAYER == 1) ? i0 : 0ull;
        u64 a1 = (LAYER == 1) ? i1 : 0ull;

        if (t > 0) {
            if (wu == 0) wait64(flags, (unsigned)t);   // peers published h(t-1)
            __syncthreads();
            const float* hb = hist + (size_t)(t - 1) * H + coff;
#pragma unroll
            for (int k = 0; k < 16; k++) {
                ULL2 hv = ldcg2(hb + 4 * k);
                fma2(a0, rw[2*k],   hv.x);
                fma2(a1, rw[2*k+1], hv.y);
            }
        }

        float p0, p1, q0, q1;
        unpack2(a0, p0, p1); unpack2(a1, q0, q1);
        float s = (p0 + p1) + (q0 + q1);
        s += __shfl_xor_sync(FULLMASK, s, 1);
        s += __shfl_xor_sync(FULLMASK, s, 2);
        s += __shfl_xor_sync(FULLMASK, s, 4);
        float iv = __shfl_sync(FULLMASK, s, cg);
        float fv = __shfl_sync(FULLMASK, s, 8 | cg);
        float gv = __shfl_sync(FULLMASK, s, 16 | cg);
        float ov = __shfl_sync(FULLMASK, s, 24 | cg);
        if (LAYER == 0) {
            const float xt = sx[t];
            iv += bi + wxi * xt; fv += bf + wxf * xt;
            gv += bg + wxg * xt; ov += bo + wxo * xt;
        } else {
            iv += bi; fv += bf; gv += bg; ov += bo;
        }
        float ii = sigfast(iv), ff = sigfast(fv), gg = tanhfast(gv), oo = sigfast(ov);
        c = ff * c + ii * gg;
        float hn = oo * tanhfast(c);

        if (l == 0) stcgf(hist + (size_t)t * H + j, hn);   // append h(t)
        __syncthreads();                                    // all 8 h stores issued
        if (tid == 0) {
            __threadfence();                                // order data before flag
            strel(flags + b * PAD, (unsigned)(t + 1));
        }

        // layer 1: xp(t+1) prefetch; overlaps flag propagation to peers
        if (LAYER == 1 && t + 1 < TT) {
            const float* hb = g_hist + (size_t)(t + 1) * H + coff;
            i0 = 0ull; i1 = 0ull;
#pragma unroll
            for (int k = 0; k < 16; k++) {
                ULL2 hv = ldg2(hb + 4 * k);
                fma2(i0, riw[2*k], hv.x); fma2(i1, riw[2*k+1], hv.y);
            }
        }
    }
}

// ---------------- MLP head on h2[T-1] ----------------
__global__ void head_kernel(const float* __restrict__ w1, const float* __restrict__ b1,
                            const float* __restrict__ w2, const float* __restrict__ b2,
                            float* __restrict__ out)
{
    __shared__ float y1[32];
    const int tid = threadIdx.x, w = tid >> 5, l = tid & 31;
    const float* hf = g_hist2 + (size_t)(TT - 1) * H;
    for (int r = w; r < 20; r += 8) {
        float acc = 0.0f;
        for (int k = l; k < H; k += 32) acc += hf[k] * w1[r * H + k];
#pragma unroll
        for (int off = 16; off; off >>= 1) acc += __shfl_xor_sync(FULLMASK, acc, off);
        if (l == 0) y1[r] = acc + b1[r];
    }
    __syncthreads();
    if (tid == 0) {
        float o = b2[0];
#pragma unroll
        for (int r = 0; r < 20; r++) o += y1[r] * w2[r];
        out[0] = o;
    }
}

extern "C" void kernel_launch(void* const* d_in, const int* in_sizes, int n_in,
                              void* d_out, int out_size)
{
    const float* x    = (const float*)d_in[0];
    const float* wih0 = (const float*)d_in[1];
    const float* whh0 = (const float*)d_in[2];
    const float* bih0 = (const float*)d_in[3];
    const float* bhh0 = (const float*)d_in[4];
    const float* wih1 = (const float*)d_in[5];
    const float* whh1 = (const float*)d_in[6];
    const float* bih1 = (const float*)d_in[7];
    const float* bhh1 = (const float*)d_in[8];
    const float* w1   = (const float*)d_in[9];
    const float* b1   = (const float*)d_in[10];
    const float* w2   = (const float*)d_in[11];
    const float* b2   = (const float*)d_in[12];
    float* out = (float*)d_out;

    init_kernel<<<1, 256>>>();
    lstm_kernel<0><<<NCTA, NTHREADS>>>(x, wih0, whh0, bih0, bhh0);
    lstm_kernel<1><<<NCTA, NTHREADS>>>(nullptr, wih1, whh1, bih1, bhh1);
    head_kernel<<<1, 256>>>(w1, b1, w2, b2, out);
}

// round 6
// speedup vs baseline: 1.3427x; 1.3427x over previous
#include <cuda_runtime.h>

#define TT 8192
#define H 512
#define NCTA 64
#define NTHREADS 256
#define FULLMASK 0xffffffffu

typedef unsigned long long u64;

// ---------------- static scratch (no allocations) ----------------
__device__ float g_h1buf[2][H];     // h1 exchange, double-buffered by superstep parity
__device__ float g_h2buf[2][H];     // h2 exchange
__device__ float g_hfinal[H];       // h2[T-1] for the MLP head
__device__ unsigned g_ctr;          // single barrier counter (the hot line)

// ---------------- helpers ----------------
struct ULL2 { u64 x, y; };

__device__ __forceinline__ ULL2 ldg2(const float* p) {   // 4 floats -> 2 packed f32x2
    ULL2 v; asm("ld.global.nc.v2.u64 {%0,%1},[%2];" : "=l"(v.x), "=l"(v.y) : "l"(p)); return v;
}
__device__ __forceinline__ ULL2 ldcg2(const float* p) {  // L2-coherent
    ULL2 v; asm volatile("ld.global.cg.v2.u64 {%0,%1},[%2];" : "=l"(v.x), "=l"(v.y) : "l"(p)); return v;
}
__device__ __forceinline__ void unpack2(u64 v, float& lo, float& hi) {
    asm("mov.b64 {%0,%1},%2;" : "=f"(lo), "=f"(hi) : "l"(v));
}
__device__ __forceinline__ void fma2(u64& acc, u64 a, u64 b) {   // 2 MACs/instr
    asm("fma.rn.f32x2 %0,%1,%2,%0;" : "+l"(acc) : "l"(a), "l"(b));
}
__device__ __forceinline__ unsigned ldacq(const unsigned* p) {
    unsigned v; asm volatile("ld.acquire.gpu.u32 %0,[%1];" : "=r"(v) : "l"(p)); return v;
}
__device__ __forceinline__ void redadd(unsigned* p) {
    asm volatile("red.relaxed.gpu.global.add.u32 [%0],1;" :: "l"(p));
}
__device__ __forceinline__ void stcgf(float* p, float v) {
    asm volatile("st.global.cg.f32 [%0],%1;" :: "l"(p), "f"(v));
}
__device__ __forceinline__ float tanhfast(float x) {
    float y; asm("tanh.approx.f32 %0,%1;" : "=f"(y) : "f"(x)); return y;
}
__device__ __forceinline__ float sigfast(float x) { return 0.5f * tanhfast(0.5f * x) + 0.5f; }

__global__ void init_kernel() { if (threadIdx.x == 0) g_ctr = 0u; }

// ---------------- fused superstep-pipelined 2-layer LSTM ----------------
// 64 CTAs x 256 threads (single wave). Superstep s: compute h1(s) [layer 0] and
// h2(s-1) [layer 1] -- independent given last superstep's publishes -> ONE
// barrier per superstep, 8193 supersteps total.
// Warp wu owns output index j = b*8+wu for BOTH layers (gate rows {j,H+j,2H+j,3H+j});
// lane l: sec = l>>3 (i/f/g/o), cg = l&7 (64-column chunk).
__global__ void __launch_bounds__(NTHREADS, 1) lstm2_kernel(
    const float* __restrict__ x,
    const float* __restrict__ wih0, const float* __restrict__ whh0,
    const float* __restrict__ bih0, const float* __restrict__ bhh0,
    const float* __restrict__ wih1, const float* __restrict__ whh1,
    const float* __restrict__ bih1, const float* __restrict__ bhh1)
{
    const int tid = threadIdx.x;
    const int wu  = tid >> 5;
    const int l   = tid & 31;
    const int cg  = l & 7;
    const int b   = blockIdx.x;
    const int j   = b * 8 + wu;
    const int row = (l >> 3) * H + j;
    const int coff = cg * 64;

    __shared__ float sx[TT];
    for (int i = tid; i < TT; i += NTHREADS) sx[i] = x[i];

    // weights -> registers: 3 x 64 floats/thread = 96 packed f32x2
    u64 w0[32], wh[32], wx[32];
    {
        const float* p = whh0 + (size_t)row * H + coff;
#pragma unroll
        for (int k = 0; k < 16; k++) { ULL2 v = ldg2(p + 4 * k); w0[2*k] = v.x; w0[2*k+1] = v.y; }
    }
    {
        const float* p = whh1 + (size_t)row * H + coff;
#pragma unroll
        for (int k = 0; k < 16; k++) { ULL2 v = ldg2(p + 4 * k); wh[2*k] = v.x; wh[2*k+1] = v.y; }
    }
    {
        const float* p = wih1 + (size_t)row * H + coff;
#pragma unroll
        for (int k = 0; k < 16; k++) { ULL2 v = ldg2(p + 4 * k); wx[2*k] = v.x; wx[2*k+1] = v.y; }
    }

    const float bi0 = bih0[j]       + bhh0[j];
    const float bf0 = bih0[H + j]   + bhh0[H + j];
    const float bg0 = bih0[2*H + j] + bhh0[2*H + j];
    const float bo0 = bih0[3*H + j] + bhh0[3*H + j];
    const float bi1 = bih1[j]       + bhh1[j];
    const float bf1 = bih1[H + j]   + bhh1[H + j];
    const float bg1 = bih1[2*H + j] + bhh1[2*H + j];
    const float bo1 = bih1[3*H + j] + bhh1[3*H + j];
    const float wxi = wih0[j], wxf = wih0[H + j], wxg = wih0[2*H + j], wxo = wih0[3*H + j];

    float c1 = 0.0f, c2 = 0.0f;   // cell states (replicated across lanes)
    __syncthreads();

    for (int s = 0; s <= TT; s++) {
        // ---- barrier: peers published h1(s-1), h2(s-2) at end of superstep s-1
        if (s > 0) {
            if (tid == 0) {
                const unsigned tgt = (unsigned)(NCTA * s);
                while (ldacq(&g_ctr) < tgt) {}
            }
            __syncthreads();
        }

        // accumulators: a = layer-0 gates row-part, e = layer-1 gates row-part
        u64 a0 = 0ull, a1 = 0ull, e0 = 0ull, e1 = 0ull;

        if (s > 0) {
            // shared load of h1(s-1): feeds BOTH layer-0 W_hh and layer-1 W_ih chains
            const float* h1p = g_h1buf[(s - 1) & 1] + coff;
#pragma unroll
            for (int k = 0; k < 16; k++) {
                ULL2 hv = ldcg2(h1p + 4 * k);
                fma2(a0, w0[2*k],   hv.x);  fma2(a1, w0[2*k+1], hv.y);
                fma2(e0, wx[2*k],   hv.x);  fma2(e1, wx[2*k+1], hv.y);
            }
        }
        if (s > 1) {
            const float* h2p = g_h2buf[(s - 2) & 1] + coff;
#pragma unroll
            for (int k = 0; k < 16; k++) {
                ULL2 hv = ldcg2(h2p + 4 * k);
                fma2(e0, wh[2*k],   hv.x);  fma2(e1, wh[2*k+1], hv.y);
            }
        }

        // ---- two parallel reductions (layer 0 sum sA, layer 1 sum sE)
        float p0, p1, q0, q1;
        unpack2(a0, p0, p1); unpack2(a1, q0, q1);
        float sA = (p0 + p1) + (q0 + q1);
        unpack2(e0, p0, p1); unpack2(e1, q0, q1);
        float sE = (p0 + p1) + (q0 + q1);
        sA += __shfl_xor_sync(FULLMASK, sA, 1);
        sE += __shfl_xor_sync(FULLMASK, sE, 1);
        sA += __shfl_xor_sync(FULLMASK, sA, 2);
        sE += __shfl_xor_sync(FULLMASK, sE, 2);
        sA += __shfl_xor_sync(FULLMASK, sA, 4);
        sE += __shfl_xor_sync(FULLMASK, sE, 4);

        // ---- layer 0: h1(s)
        if (s < TT) {
            float iv = __shfl_sync(FULLMASK, sA, cg);
            float fv = __shfl_sync(FULLMASK, sA, 8 | cg);
            float gv = __shfl_sync(FULLMASK, sA, 16 | cg);
            float ov = __shfl_sync(FULLMASK, sA, 24 | cg);
            const float xt = sx[s];
            iv += bi0 + wxi * xt; fv += bf0 + wxf * xt;
            gv += bg0 + wxg * xt; ov += bo0 + wxo * xt;
            float ii = sigfast(iv), ff = sigfast(fv), gg = tanhfast(gv), oo = sigfast(ov);
            c1 = ff * c1 + ii * gg;
            float h1n = oo * tanhfast(c1);
            if (l == 0) stcgf(g_h1buf[s & 1] + j, h1n);
        }
        // ---- layer 1: h2(s-1)
        if (s >= 1) {
            float iv = __shfl_sync(FULLMASK, sE, cg)      + bi1;
            float fv = __shfl_sync(FULLMASK, sE, 8 | cg)  + bf1;
            float gv = __shfl_sync(FULLMASK, sE, 16 | cg) + bg1;
            float ov = __shfl_sync(FULLMASK, sE, 24 | cg) + bo1;
            float ii = sigfast(iv), ff = sigfast(fv), gg = tanhfast(gv), oo = sigfast(ov);
            c2 = ff * c2 + ii * gg;
            float h2n = oo * tanhfast(c2);
            if (l == 0) {
                stcgf(g_h2buf[(s - 1) & 1] + j, h2n);
                if (s == TT) stcgf(g_hfinal + j, h2n);
            }
        }

        // ---- publish: all stores issued CTA-wide, then one arrival on the counter
        __syncthreads();
        if (tid == 0) { __threadfence(); redadd(&g_ctr); }
    }
}

// ---------------- MLP head on h2[T-1] ----------------
__global__ void head_kernel(const float* __restrict__ w1, const float* __restrict__ b1,
                            const float* __restrict__ w2, const float* __restrict__ b2,
                            float* __restrict__ out)
{
    __shared__ float y1[32];
    const int tid = threadIdx.x, w = tid >> 5, l = tid & 31;
    for (int r = w; r < 20; r += 8) {
        float acc = 0.0f;
        for (int k = l; k < H; k += 32) acc += g_hfinal[k] * w1[r * H + k];
#pragma unroll
        for (int off = 16; off; off >>= 1) acc += __shfl_xor_sync(FULLMASK, acc, off);
        if (l == 0) y1[r] = acc + b1[r];
    }
    __syncthreads();
    if (tid == 0) {
        float o = b2[0];
#pragma unroll
        for (int r = 0; r < 20; r++) o += y1[r] * w2[r];
        out[0] = o;
    }
}

extern "C" void kernel_launch(void* const* d_in, const int* in_sizes, int n_in,
                              void* d_out, int out_size)
{
    const float* x    = (const float*)d_in[0];
    const float* wih0 = (const float*)d_in[1];
    const float* whh0 = (const float*)d_in[2];
    const float* bih0 = (const float*)d_in[3];
    const float* bhh0 = (const float*)d_in[4];
    const float* wih1 = (const float*)d_in[5];
    const float* whh1 = (const float*)d_in[6];
    const float* bih1 = (const float*)d_in[7];
    const float* bhh1 = (const float*)d_in[8];
    const float* w1   = (const float*)d_in[9];
    const float* b1   = (const float*)d_in[10];
    const float* w2   = (const float*)d_in[11];
    const float* b2   = (const float*)d_in[12];
    float* out = (float*)d_out;

    init_kernel<<<1, 32>>>();
    lstm2_kernel<<<NCTA, NTHREADS>>>(x, wih0, whh0, bih0, bhh0,
                                     wih1, whh1, bih1, bhh1);
    head_kernel<<<1, 256>>>(w1, b1, w2, b2, out);
}